// round 8
// baseline (speedup 1.0000x reference)
#include <cuda_runtime.h>
#include <cuda_fp16.h>
#include <cstdint>

#define CIN 64
#define COUT 64
#define HH 128
#define WW 128
#define BB 4
#define NTHREADS 256
#define XPAD 136            // x extent incl. halo/pad
#define XPC2 36             // words per x in s_in (32 c2 + 4 pad) -> ldmatrix conflict-free
#define NSLOT 4             // weight ring slots (8 KB h-tiles)
#define TILE_BYTES 8192

// ---- smem byte offsets ----
#define OFF_FULL  0         // 4 x 8B
#define OFF_EMPTY 32        // 4 x 8B
#define OFF_D     64        // 3 x 136 floats = 1632
#define OFF_LO    1696      // 3 x 128 floats = 1536
#define OFF_HI    3232      // 3 x 128 floats = 1536
#define OFF_BIAS  4768      // 64 floats
#define OFF_IN    5120      // 3 rows x 136 x x 36 words = 58752 B  [r][x][c2]
#define OFF_W     63872     // 4 slots x 8192 B = 32768
#define SMEM_TOTAL 96640

// Fragment-ordered f16 weights: [tile=tap*3+h][kc4][nt8][lane32][j2] (u32 = half2)
__device__ uint32_t g_wf[27 * 2048];

__global__ void prep_w_kernel(const float* __restrict__ w) {
    int idx = blockIdx.x * blockDim.x + threadIdx.x;
    if (idx >= 27 * 2048) return;
    int j    = idx & 1;
    int lane = (idx >> 1) & 31;
    int nt   = (idx >> 6) & 7;
    int kc   = (idx >> 9) & 3;
    int tile = idx >> 11;
    int h = tile % 3, tap = tile / 3;
    int k0 = kc * 16 + (lane & 3) * 2 + j * 8;
    int o  = nt * 8 + (lane >> 2);
    // source layout: [h][o][c][ky][kx]
    float v0 = w[(((h * COUT + o) * CIN + k0) * 9) + tap];
    float v1 = w[(((h * COUT + o) * CIN + k0 + 1) * 9) + tap];
    __half2 p = __floats2half2_rn(v0, v1);
    g_wf[idx] = *reinterpret_cast<uint32_t*>(&p);
}

// ---- PTX helpers ----
__device__ __forceinline__ uint32_t smem_u32(const void* p) {
    uint32_t a;
    asm("{ .reg .u64 t; cvta.to.shared.u64 t, %1; cvt.u32.u64 %0, t; }" : "=r"(a) : "l"(p));
    return a;
}
__device__ __forceinline__ void mbar_init(uint32_t m, uint32_t cnt) {
    asm volatile("mbarrier.init.shared.b64 [%0], %1;" :: "r"(m), "r"(cnt) : "memory");
}
__device__ __forceinline__ void mbar_arrive(uint32_t m) {
    asm volatile("mbarrier.arrive.shared.b64 _, [%0];" :: "r"(m) : "memory");
}
__device__ __forceinline__ void mbar_expect_tx(uint32_t m, uint32_t bytes) {
    asm volatile("mbarrier.arrive.expect_tx.shared.b64 _, [%0], %1;" :: "r"(m), "r"(bytes) : "memory");
}
__device__ __forceinline__ void bulk_cp(uint32_t dst, const void* src, uint32_t bytes, uint32_t m) {
    asm volatile("cp.async.bulk.shared::cta.global.mbarrier::complete_tx::bytes [%0], [%1], %2, [%3];"
                 :: "r"(dst), "l"(src), "r"(bytes), "r"(m) : "memory");
}
__device__ __forceinline__ void mbar_wait(uint32_t m, uint32_t parity) {
    uint32_t done;
    asm volatile("{\n\t.reg .pred p;\n\t"
                 "mbarrier.try_wait.parity.acquire.cta.shared::cta.b64 p, [%1], %2;\n\t"
                 "selp.b32 %0, 1, 0, p;\n\t}"
                 : "=r"(done) : "r"(m), "r"(parity) : "memory");
    if (!done) {
        asm volatile("{\n\t.reg .pred P1;\n\t"
                     "W_%=:\n\t"
                     "mbarrier.try_wait.parity.acquire.cta.shared::cta.b64 P1, [%0], %1, 0x989680;\n\t"
                     "@P1 bra.uni D_%=;\n\t"
                     "bra.uni W_%=;\n\t"
                     "D_%=:\n\t}" :: "r"(m), "r"(parity) : "memory");
    }
}
__device__ __forceinline__ void ldmx4(uint32_t* r, uint32_t addr) {
    asm volatile("ldmatrix.sync.aligned.m8n8.x4.shared.b16 {%0,%1,%2,%3}, [%4];"
                 : "=r"(r[0]), "=r"(r[1]), "=r"(r[2]), "=r"(r[3]) : "r"(addr));
}
__device__ __forceinline__ void mma_f16(float& d0, float& d1, float& d2, float& d3,
                                        uint32_t a0, uint32_t a1, uint32_t a2, uint32_t a3,
                                        uint32_t b0, uint32_t b1) {
    asm volatile("mma.sync.aligned.m16n8k16.row.col.f32.f16.f16.f32 "
                 "{%0,%1,%2,%3}, {%4,%5,%6,%7}, {%8,%9}, {%0,%1,%2,%3};"
                 : "+f"(d0), "+f"(d1), "+f"(d2), "+f"(d3)
                 : "r"(a0), "r"(a1), "r"(a2), "r"(a3), "r"(b0), "r"(b1));
}

__global__ __launch_bounds__(NTHREADS, 2)
void conv25d_mma_kernel(const float* __restrict__ inp, const float* __restrict__ dep,
                        const float* __restrict__ bias, const void* __restrict__ fptr,
                        float* __restrict__ out) {
    extern __shared__ char smem[];
    const uint32_t sb = smem_u32(smem);
    const int tid  = threadIdx.x;
    const int wid  = tid >> 5;
    const int lane = tid & 31;
    const int mw   = wid & 3;      // M warp: px [mw*32, mw*32+32)
    const int nw   = wid >> 2;     // N warp: o  [nw*32, nw*32+32)
    const int y    = blockIdx.x;
    const int b    = blockIdx.y;

    float*     s_d    = (float*)(smem + OFF_D);
    float*     s_lo   = (float*)(smem + OFF_LO);
    float*     s_hi   = (float*)(smem + OFF_HI);
    float*     s_bias = (float*)(smem + OFF_BIAS);
    uint32_t*  s_in   = (uint32_t*)(smem + OFF_IN);
    const uint32_t mb_full  = sb + OFF_FULL;
    const uint32_t mb_empty = sb + OFF_EMPTY;
    const uint32_t wsm      = sb + OFF_W;

    if (tid == 0) {
        for (int s = 0; s < NSLOT; s++) {
            mbar_init(mb_full + 8 * s, 1);
            mbar_init(mb_empty + 8 * s, 8);   // one arrive per warp
        }
    }
    __syncthreads();
    if (tid == 0) {
        asm volatile("fence.proxy.async.shared::cta;" ::: "memory");
        for (int t = 0; t < NSLOT; t++) {
            mbar_expect_tx(mb_full + 8 * t, TILE_BYTES);
            bulk_cp(wsm + t * TILE_BYTES, g_wf + t * 2048, TILE_BYTES, mb_full + 8 * t);
        }
    }

    // scalar f (int or float bits)
    unsigned fu = *reinterpret_cast<const unsigned*>(fptr);
    float fval = (fu > 0u && fu < (1u << 24)) ? (float)fu : __uint_as_float(fu);

    // depth rows y-1..y+1 (padded), bin bounds, bias
    const float* db = dep + (long)b * HH * WW;
    for (int i = tid; i < 3 * XPAD; i += NTHREADS) {
        int xx = i % XPAD, r = i / XPAD;
        int gx = xx - 1, gy = y + r - 1;
        float v = 0.f;
        if ((unsigned)gx < (unsigned)WW && (unsigned)gy < (unsigned)HH) v = db[gy * WW + gx];
        s_d[i] = v;
    }
    if (tid < 128) {
        float d0 = db[y * WW + tid];
        float s0 = __fdiv_rn(d0, fval);
        float hv = __fmul_rn(s0, 0.5f);
#pragma unroll
        for (int h = 0; h < 3; h++) {
            float z0 = __fadd_rn(d0, __fmul_rn((float)(h - 1), s0));
            s_lo[h * 128 + tid] = __fsub_rn(z0, hv);
            s_hi[h * 128 + tid] = __fadd_rn(z0, hv);
        }
    }
    if (tid < 64) s_bias[tid] = bias[tid];

    // stage input rows y-1..y+1 as half2, layout [r][x][c2]
    const float* inb = inp + ((long)b * CIN) * HH * WW;
    for (int i = tid; i < 3 * 32 * XPAD; i += NTHREADS) {
        int xx = i % XPAD;
        int c2 = (i / XPAD) % 32;
        int r  = i / (XPAD * 32);
        int gx = xx - 1, gy = y + r - 1;
        uint32_t u = 0u;
        if ((unsigned)gx < (unsigned)WW && (unsigned)gy < (unsigned)HH) {
            float f0 = inb[((2 * c2) * HH + gy) * WW + gx];
            float f1 = inb[((2 * c2 + 1) * HH + gy) * WW + gx];
            __half2 p = __floats2half2_rn(f0, f1);
            u = *reinterpret_cast<uint32_t*>(&p);
        }
        s_in[(r * XPAD + xx) * XPC2 + c2] = u;
    }
    __syncthreads();

    // ldmatrix lane address components
    const int t4     = lane >> 3;
    const int p_lane = mw * 32 + (t4 & 1) * 8 + (lane & 7);
    const int c2off  = (t4 >> 1) * 4;
    const int pxl4   = mw * 32 + (lane >> 2);

    float d[2][4][4];
#pragma unroll
    for (int mt = 0; mt < 2; mt++)
#pragma unroll
        for (int nt = 0; nt < 4; nt++)
#pragma unroll
            for (int r = 0; r < 4; r++) d[mt][nt][r] = 0.f;

#pragma unroll 1
    for (int tap = 0; tap < 9; tap++) {
        const int ky = tap / 3, kx = tap % 3;

        // wait the 3 h-tiles for this tap
        const uint2* bh[3];
#pragma unroll
        for (int h = 0; h < 3; h++) {
            int T = 3 * tap + h, s = T & 3;
            mbar_wait(mb_full + 8 * s, (T >> 2) & 1);
            bh[h] = (const uint2*)(smem + OFF_W + s * TILE_BYTES) + (nw * 4) * 32 + lane;
        }

        // hoist this tap's A fragments: 8 ldmatrix.x4
        uint32_t A[4][2][4];
        const uint32_t abase = sb + OFF_IN +
            4u * (uint32_t)((ky * XPAD + p_lane + kx) * XPC2 + c2off);
#pragma unroll
        for (int kc = 0; kc < 4; kc++)
#pragma unroll
            for (int mt = 0; mt < 2; mt++)
                ldmx4(A[kc][mt], abase + 4u * (uint32_t)(mt * 16 * XPC2 + kc * 8));

        // masks for this tap
        uint32_t msk[3][4];
#pragma unroll
        for (int i = 0; i < 4; i++) {
            float dw = s_d[ky * XPAD + pxl4 + i * 8 + kx];
#pragma unroll
            for (int h = 0; h < 3; h++) {
                float lo = s_lo[h * 128 + pxl4 + i * 8];
                float hi = s_hi[h * 128 + pxl4 + i * 8];
                msk[h][i] = (dw >= lo && dw < hi) ? 0xFFFFFFFFu : 0u;
            }
        }

#pragma unroll
        for (int h = 0; h < 3; h++) {
#pragma unroll
            for (int kc = 0; kc < 4; kc++) {
                const uint2* bp = bh[h] + (kc * 8) * 32;
                uint2 bf[4];
#pragma unroll
                for (int nt = 0; nt < 4; nt++) bf[nt] = bp[nt * 32];
#pragma unroll
                for (int mt = 0; mt < 2; mt++) {
                    uint32_t a0 = A[kc][mt][0] & msk[h][2 * mt];
                    uint32_t a1 = A[kc][mt][1] & msk[h][2 * mt + 1];
                    uint32_t a2 = A[kc][mt][2] & msk[h][2 * mt];
                    uint32_t a3 = A[kc][mt][3] & msk[h][2 * mt + 1];
#pragma unroll
                    for (int nt = 0; nt < 4; nt++)
                        mma_f16(d[mt][nt][0], d[mt][nt][1], d[mt][nt][2], d[mt][nt][3],
                                a0, a1, a2, a3, bf[nt].x, bf[nt].y);
                }
            }
        }

        // release slots
        if (lane == 0) {
#pragma unroll
            for (int h = 0; h < 3; h++) mbar_arrive(mb_empty + 8 * ((3 * tap + h) & 3));
        }
        // producer: keep ring NSLOT tiles ahead
        if (tid == 0) {
#pragma unroll
            for (int h = 0; h < 3; h++) {
                int T = 3 * tap + NSLOT + h;
                if (T > 26) break;
                int s = T & 3, r = T >> 2;
                mbar_wait(mb_empty + 8 * s, (r - 1) & 1);
                mbar_expect_tx(mb_full + 8 * s, TILE_BYTES);
                bulk_cp(wsm + s * TILE_BYTES, g_wf + T * 2048, TILE_BYTES, mb_full + 8 * s);
            }
        }
    }

    // epilogue: bias + store. out[b][o][y][px]
    float* ob = out + ((long)b * COUT * HH + y) * WW;
#pragma unroll
    for (int mt = 0; mt < 2; mt++) {
        int pxr = mw * 32 + mt * 16 + (lane >> 2);
#pragma unroll
        for (int nt = 0; nt < 4; nt++) {
            int o = nw * 32 + nt * 8 + 2 * (lane & 3);
            float b0 = s_bias[o], b1 = s_bias[o + 1];
            float* p0 = ob + (long)o * HH * WW + pxr;
            float* p1 = p0 + HH * WW;
            p0[0] = d[mt][nt][0] + b0;
            p1[0] = d[mt][nt][1] + b1;
            p0[8] = d[mt][nt][2] + b0;
            p1[8] = d[mt][nt][3] + b1;
        }
    }
}

extern "C" void kernel_launch(void* const* d_in, const int* in_sizes, int n_in,
                              void* d_out, int out_size) {
    const float* inputs = (const float*)d_in[0];
    const float* depth  = (const float*)d_in[1];
    const float* weight = (const float*)d_in[2];
    const float* bias   = (const float*)d_in[3];
    const void*  f      = d_in[4];
    float* out = (float*)d_out;

    prep_w_kernel<<<(27 * 2048 + 255) / 256, 256>>>(weight);

    cudaFuncSetAttribute(conv25d_mma_kernel, cudaFuncAttributeMaxDynamicSharedMemorySize,
                         SMEM_TOTAL);
    dim3 grid(HH, BB);
    conv25d_mma_kernel<<<grid, NTHREADS, SMEM_TOTAL>>>(inputs, depth, bias, f, out);
}

// round 9
// speedup vs baseline: 1.0977x; 1.0977x over previous
#include <cuda_runtime.h>
#include <cuda_fp16.h>
#include <cstdint>

#define CIN 64
#define COUT 64
#define HH 128
#define WW 128
#define BB 4
#define NTHREADS 512
#define XPAD 136            // x extent incl. halo/pad
#define XPC2 36             // words per x in s_in (32 c2 + 4 pad) -> ldmatrix conflict-free
#define NSLOT 8             // weight ring slots (8 KB h-tiles)
#define TILE_BYTES 8192
#define NQ 54               // 2 passes x 27 tiles

// ---- smem byte offsets ----
#define OFF_FULL  0         // 8 x 8B
#define OFF_EMPTY 64        // 8 x 8B
#define OFF_D     128       // 6 x 136 floats = 3264
#define OFF_LO    3392      // 3 x 512 floats = 6144
#define OFF_HI    9536      // 3 x 512 floats = 6144
#define OFF_BIAS  15680     // 64 floats
#define OFF_IN    15936     // 6 rows x 136 x x 36 words = 117504 B  [r][x][c2]
#define OFF_W     133440    // 8 slots x 8192 B = 65536
#define SMEM_TOTAL 198976

// Fragment-ordered f16 weights: [tile=tap*3+h][kc4][nt8][lane32][j2] (u32 = half2)
__device__ uint32_t g_wf[27 * 2048];

__global__ void prep_w_kernel(const float* __restrict__ w) {
    int idx = blockIdx.x * blockDim.x + threadIdx.x;
    if (idx >= 27 * 2048) return;
    int j    = idx & 1;
    int lane = (idx >> 1) & 31;
    int nt   = (idx >> 6) & 7;
    int kc   = (idx >> 9) & 3;
    int tile = idx >> 11;
    int h = tile % 3, tap = tile / 3;
    int k0 = kc * 16 + (lane & 3) * 2 + j * 8;
    int o  = nt * 8 + (lane >> 2);
    // source layout: [h][o][c][ky][kx]
    float v0 = w[(((h * COUT + o) * CIN + k0) * 9) + tap];
    float v1 = w[(((h * COUT + o) * CIN + k0 + 1) * 9) + tap];
    __half2 p = __floats2half2_rn(v0, v1);
    g_wf[idx] = *reinterpret_cast<uint32_t*>(&p);
}

// ---- PTX helpers ----
__device__ __forceinline__ uint32_t smem_u32(const void* p) {
    uint32_t a;
    asm("{ .reg .u64 t; cvta.to.shared.u64 t, %1; cvt.u32.u64 %0, t; }" : "=r"(a) : "l"(p));
    return a;
}
__device__ __forceinline__ void mbar_init(uint32_t m, uint32_t cnt) {
    asm volatile("mbarrier.init.shared.b64 [%0], %1;" :: "r"(m), "r"(cnt) : "memory");
}
__device__ __forceinline__ void mbar_arrive(uint32_t m) {
    asm volatile("mbarrier.arrive.shared.b64 _, [%0];" :: "r"(m) : "memory");
}
__device__ __forceinline__ void mbar_expect_tx(uint32_t m, uint32_t bytes) {
    asm volatile("mbarrier.arrive.expect_tx.shared.b64 _, [%0], %1;" :: "r"(m), "r"(bytes) : "memory");
}
__device__ __forceinline__ void bulk_cp(uint32_t dst, const void* src, uint32_t bytes, uint32_t m) {
    asm volatile("cp.async.bulk.shared::cta.global.mbarrier::complete_tx::bytes [%0], [%1], %2, [%3];"
                 :: "r"(dst), "l"(src), "r"(bytes), "r"(m) : "memory");
}
__device__ __forceinline__ void mbar_wait(uint32_t m, uint32_t parity) {
    uint32_t done;
    asm volatile("{\n\t.reg .pred p;\n\t"
                 "mbarrier.try_wait.parity.acquire.cta.shared::cta.b64 p, [%1], %2;\n\t"
                 "selp.b32 %0, 1, 0, p;\n\t}"
                 : "=r"(done) : "r"(m), "r"(parity) : "memory");
    if (!done) {
        asm volatile("{\n\t.reg .pred P1;\n\t"
                     "W_%=:\n\t"
                     "mbarrier.try_wait.parity.acquire.cta.shared::cta.b64 P1, [%0], %1, 0x989680;\n\t"
                     "@P1 bra.uni D_%=;\n\t"
                     "bra.uni W_%=;\n\t"
                     "D_%=:\n\t}" :: "r"(m), "r"(parity) : "memory");
    }
}
__device__ __forceinline__ void ldmx4(uint32_t* r, uint32_t addr) {
    asm volatile("ldmatrix.sync.aligned.m8n8.x4.shared.b16 {%0,%1,%2,%3}, [%4];"
                 : "=r"(r[0]), "=r"(r[1]), "=r"(r[2]), "=r"(r[3]) : "r"(addr));
}
__device__ __forceinline__ void mma_f16(float& d0, float& d1, float& d2, float& d3,
                                        uint32_t a0, uint32_t a1, uint32_t a2, uint32_t a3,
                                        uint32_t b0, uint32_t b1) {
    asm volatile("mma.sync.aligned.m16n8k16.row.col.f32.f16.f16.f32 "
                 "{%0,%1,%2,%3}, {%4,%5,%6,%7}, {%8,%9}, {%0,%1,%2,%3};"
                 : "+f"(d0), "+f"(d1), "+f"(d2), "+f"(d3)
                 : "r"(a0), "r"(a1), "r"(a2), "r"(a3), "r"(b0), "r"(b1));
}

__global__ __launch_bounds__(NTHREADS, 1)
void conv25d_mma_kernel(const float* __restrict__ inp, const float* __restrict__ dep,
                        const float* __restrict__ bias, const void* __restrict__ fptr,
                        float* __restrict__ out) {
    extern __shared__ char smem[];
    const uint32_t sb = smem_u32(smem);
    const int tid  = threadIdx.x;
    const int wid  = tid >> 5;
    const int lane = tid & 31;
    const int mw   = wid & 7;      // 4 x-quarters x 2 row-slots
    const int nw   = wid >> 3;     // N warp: o [nw*32, nw*32+32)
    const int rs   = mw >> 2;      // row-slot within a pass (0/1)
    const int y0   = blockIdx.x * 4;
    const int b    = blockIdx.y;

    float*     s_d    = (float*)(smem + OFF_D);
    float*     s_lo   = (float*)(smem + OFF_LO);
    float*     s_hi   = (float*)(smem + OFF_HI);
    float*     s_bias = (float*)(smem + OFF_BIAS);
    uint32_t*  s_in   = (uint32_t*)(smem + OFF_IN);
    const uint32_t mb_full  = sb + OFF_FULL;
    const uint32_t mb_empty = sb + OFF_EMPTY;
    const uint32_t wsm      = sb + OFF_W;

    if (tid == 0) {
        for (int s = 0; s < NSLOT; s++) {
            mbar_init(mb_full + 8 * s, 1);
            mbar_init(mb_empty + 8 * s, 16);   // one arrive per warp
        }
    }
    __syncthreads();
    if (tid == 0) {
        asm volatile("fence.proxy.async.shared::cta;" ::: "memory");
        for (int q = 0; q < NSLOT; q++) {
            mbar_expect_tx(mb_full + 8 * q, TILE_BYTES);
            bulk_cp(wsm + q * TILE_BYTES, g_wf + q * 2048, TILE_BYTES, mb_full + 8 * q);
        }
    }

    // scalar f (int or float bits)
    unsigned fu = *reinterpret_cast<const unsigned*>(fptr);
    float fval = (fu > 0u && fu < (1u << 24)) ? (float)fu : __uint_as_float(fu);

    // depth rows y0-1..y0+4 (padded), bin bounds for 4 rows, bias
    const float* db = dep + (long)b * HH * WW;
    for (int i = tid; i < 6 * XPAD; i += NTHREADS) {
        int xx = i % XPAD, r = i / XPAD;
        int gx = xx - 1, gy = y0 + r - 1;
        float v = 0.f;
        if ((unsigned)gx < (unsigned)WW && (unsigned)gy < (unsigned)HH) v = db[gy * WW + gx];
        s_d[i] = v;
    }
    {
        int x = tid & 127, yy = y0 + (tid >> 7);   // tid covers 4 rows x 128
        float d0 = db[yy * WW + x];
        float s0 = __fdiv_rn(d0, fval);
        float hv = __fmul_rn(s0, 0.5f);
#pragma unroll
        for (int h = 0; h < 3; h++) {
            float z0 = __fadd_rn(d0, __fmul_rn((float)(h - 1), s0));
            s_lo[h * 512 + tid] = __fsub_rn(z0, hv);
            s_hi[h * 512 + tid] = __fadd_rn(z0, hv);
        }
    }
    if (tid < 64) s_bias[tid] = bias[tid];

    // stage input rows y0-1..y0+4 as half2, layout [r][x][c2]
    const float* inb = inp + ((long)b * CIN) * HH * WW;
    for (int i = tid; i < 6 * 32 * XPAD; i += NTHREADS) {
        int xx = i % XPAD;
        int c2 = (i / XPAD) % 32;
        int r  = i / (XPAD * 32);
        int gx = xx - 1, gy = y0 + r - 1;
        uint32_t u = 0u;
        if ((unsigned)gx < (unsigned)WW && (unsigned)gy < (unsigned)HH) {
            float f0 = inb[((2 * c2) * HH + gy) * WW + gx];
            float f1 = inb[((2 * c2 + 1) * HH + gy) * WW + gx];
            __half2 p = __floats2half2_rn(f0, f1);
            u = *reinterpret_cast<uint32_t*>(&p);
        }
        s_in[(r * XPAD + xx) * XPC2 + c2] = u;
    }
    __syncthreads();

    // lane address components
    const int t4     = lane >> 3;
    const int x_lane = (mw & 3) * 32 + (t4 & 1) * 8 + (lane & 7);  // ldmatrix x
    const int c2off  = (t4 >> 1) * 4;
    const int x4     = (mw & 3) * 32 + (lane >> 2);                // mask-owner x

#pragma unroll 1
    for (int pass = 0; pass < 2; pass++) {
        const int row4 = 2 * pass + rs;          // row index within the 4 output rows
        const int qb0  = pass * 27;

        float d[2][4][4];
#pragma unroll
        for (int mt = 0; mt < 2; mt++)
#pragma unroll
            for (int nt = 0; nt < 4; nt++)
#pragma unroll
                for (int r = 0; r < 4; r++) d[mt][nt][r] = 0.f;

#pragma unroll 1
        for (int tap = 0; tap < 9; tap++) {
            const int ky = tap / 3, kx = tap % 3;
            const int qb = qb0 + 3 * tap;

            // wait the 3 h-tiles for this tap
            const uint2* bh[3];
#pragma unroll
            for (int h = 0; h < 3; h++) {
                int q = qb + h, s = q & 7;
                mbar_wait(mb_full + 8 * s, (q >> 3) & 1);
                bh[h] = (const uint2*)(smem + OFF_W + s * TILE_BYTES) + (nw * 4) * 32 + lane;
            }

            // hoist this tap's A fragments: 8 ldmatrix.x4
            uint32_t A[4][2][4];
            const uint32_t abase = sb + OFF_IN +
                4u * (uint32_t)(((row4 + ky) * XPAD + x_lane + kx) * XPC2 + c2off);
#pragma unroll
            for (int kc = 0; kc < 4; kc++)
#pragma unroll
                for (int mt = 0; mt < 2; mt++)
                    ldmx4(A[kc][mt], abase + 4u * (uint32_t)(mt * 16 * XPC2 + kc * 8));

            // masks for this tap
            uint32_t msk[3][4];
#pragma unroll
            for (int i = 0; i < 4; i++) {
                float dw = s_d[(row4 + ky) * XPAD + x4 + i * 8 + kx];
                int pg = row4 * 128 + x4 + i * 8;
#pragma unroll
                for (int h = 0; h < 3; h++) {
                    float lo = s_lo[h * 512 + pg];
                    float hi = s_hi[h * 512 + pg];
                    msk[h][i] = (dw >= lo && dw < hi) ? 0xFFFFFFFFu : 0u;
                }
            }

#pragma unroll
            for (int h = 0; h < 3; h++) {
#pragma unroll
                for (int kc = 0; kc < 4; kc++) {
                    const uint2* bp = bh[h] + (kc * 8) * 32;
                    uint2 bf[4];
#pragma unroll
                    for (int nt = 0; nt < 4; nt++) bf[nt] = bp[nt * 32];
#pragma unroll
                    for (int mt = 0; mt < 2; mt++) {
                        uint32_t a0 = A[kc][mt][0] & msk[h][2 * mt];
                        uint32_t a1 = A[kc][mt][1] & msk[h][2 * mt + 1];
                        uint32_t a2 = A[kc][mt][2] & msk[h][2 * mt];
                        uint32_t a3 = A[kc][mt][3] & msk[h][2 * mt + 1];
#pragma unroll
                        for (int nt = 0; nt < 4; nt++)
                            mma_f16(d[mt][nt][0], d[mt][nt][1], d[mt][nt][2], d[mt][nt][3],
                                    a0, a1, a2, a3, bf[nt].x, bf[nt].y);
                    }
                }
            }

            // release slots
            if (lane == 0) {
#pragma unroll
                for (int h = 0; h < 3; h++) mbar_arrive(mb_empty + 8 * ((qb + h) & 7));
            }
            // producer: keep ring NSLOT requests ahead
            if (tid == 0) {
#pragma unroll
                for (int h = 0; h < 3; h++) {
                    int qn = qb + NSLOT + h;
                    if (qn >= NQ) break;
                    int s = qn & 7, r = qn >> 3;
                    mbar_wait(mb_empty + 8 * s, (r - 1) & 1);
                    mbar_expect_tx(mb_full + 8 * s, TILE_BYTES);
                    bulk_cp(wsm + s * TILE_BYTES, g_wf + (qn % 27) * 2048, TILE_BYTES,
                            mb_full + 8 * s);
                }
            }
        }

        // epilogue for this pass: bias + store. out[b][o][y0+row4][px]
        float* ob = out + ((long)b * COUT * HH + (y0 + row4)) * WW;
#pragma unroll
        for (int mt = 0; mt < 2; mt++) {
            int pxr = (mw & 3) * 32 + mt * 16 + (lane >> 2);
#pragma unroll
            for (int nt = 0; nt < 4; nt++) {
                int o = nw * 32 + nt * 8 + 2 * (lane & 3);
                float b0 = s_bias[o], b1 = s_bias[o + 1];
                float* p0 = ob + (long)o * HH * WW + pxr;
                float* p1 = p0 + HH * WW;
                p0[0] = d[mt][nt][0] + b0;
                p1[0] = d[mt][nt][1] + b1;
                p0[8] = d[mt][nt][2] + b0;
                p1[8] = d[mt][nt][3] + b1;
            }
        }
    }
}

extern "C" void kernel_launch(void* const* d_in, const int* in_sizes, int n_in,
                              void* d_out, int out_size) {
    const float* inputs = (const float*)d_in[0];
    const float* depth  = (const float*)d_in[1];
    const float* weight = (const float*)d_in[2];
    const float* bias   = (const float*)d_in[3];
    const void*  f      = d_in[4];
    float* out = (float*)d_out;

    prep_w_kernel<<<(27 * 2048 + 255) / 256, 256>>>(weight);

    cudaFuncSetAttribute(conv25d_mma_kernel, cudaFuncAttributeMaxDynamicSharedMemorySize,
                         SMEM_TOTAL);
    dim3 grid(HH / 4, BB);
    conv25d_mma_kernel<<<grid, NTHREADS, SMEM_TOTAL>>>(inputs, depth, bias, f, out);
}

// round 11
// speedup vs baseline: 1.2024x; 1.0953x over previous
#include <cuda_runtime.h>
#include <cuda_fp16.h>
#include <cstdint>

#define CIN 64
#define COUT 64
#define HH 128
#define WW 128
#define BB 4
#define NTHREADS 512
#define XPAD 136            // x extent incl. halo/pad
#define XPC2 36             // words per x in s_in (32 c2 + 4 pad) -> ldmatrix conflict-free
#define TILE_BYTES 8192
#define GROUP_BYTES 24576   // 3 h-tiles, one mbarrier
#define NQ 18               // 2 passes x 9 tap-groups

// ---- smem byte offsets ----
#define OFF_FULL  0         // 2 x 8B
#define OFF_EMPTY 16        // 2 x 8B
#define OFF_D     64        // 6 x 136 floats = 3264
#define OFF_LO    3328      // 3 x 512 floats = 6144
#define OFF_HI    9472      // 3 x 512 floats = 6144
#define OFF_BIAS  15616     // 64 floats
#define OFF_IN    15872     // 6 rows x 136 x x 36 words = 117504 B  [r][x][c2]
#define OFF_W     133376    // 2 groups x 24576 B = 49152
#define SMEM_TOTAL 182528

// Fragment-ordered f16 weights: [tile=tap*3+h][kc4][nt8][lane32][j2] (u32 = half2)
__device__ uint32_t g_wf[27 * 2048];

__global__ void prep_w_kernel(const float* __restrict__ w) {
    int idx = blockIdx.x * blockDim.x + threadIdx.x;
    if (idx >= 27 * 2048) return;
    int j    = idx & 1;
    int lane = (idx >> 1) & 31;
    int nt   = (idx >> 6) & 7;
    int kc   = (idx >> 9) & 3;
    int tile = idx >> 11;
    int h = tile % 3, tap = tile / 3;
    int k0 = kc * 16 + (lane & 3) * 2 + j * 8;
    int o  = nt * 8 + (lane >> 2);
    // source layout: [h][o][c][ky][kx]
    float v0 = w[(((h * COUT + o) * CIN + k0) * 9) + tap];
    float v1 = w[(((h * COUT + o) * CIN + k0 + 1) * 9) + tap];
    __half2 p = __floats2half2_rn(v0, v1);
    g_wf[idx] = *reinterpret_cast<uint32_t*>(&p);
}

// ---- PTX helpers ----
__device__ __forceinline__ uint32_t smem_u32(const void* p) {
    uint32_t a;
    asm("{ .reg .u64 t; cvta.to.shared.u64 t, %1; cvt.u32.u64 %0, t; }" : "=r"(a) : "l"(p));
    return a;
}
__device__ __forceinline__ void mbar_init(uint32_t m, uint32_t cnt) {
    asm volatile("mbarrier.init.shared.b64 [%0], %1;" :: "r"(m), "r"(cnt) : "memory");
}
__device__ __forceinline__ void mbar_arrive(uint32_t m) {
    asm volatile("mbarrier.arrive.shared.b64 _, [%0];" :: "r"(m) : "memory");
}
__device__ __forceinline__ void mbar_expect_tx(uint32_t m, uint32_t bytes) {
    asm volatile("mbarrier.arrive.expect_tx.shared.b64 _, [%0], %1;" :: "r"(m), "r"(bytes) : "memory");
}
__device__ __forceinline__ void bulk_cp(uint32_t dst, const void* src, uint32_t bytes, uint32_t m) {
    asm volatile("cp.async.bulk.shared::cta.global.mbarrier::complete_tx::bytes [%0], [%1], %2, [%3];"
                 :: "r"(dst), "l"(src), "r"(bytes), "r"(m) : "memory");
}
__device__ __forceinline__ void mbar_wait(uint32_t m, uint32_t parity) {
    uint32_t done;
    asm volatile("{\n\t.reg .pred p;\n\t"
                 "mbarrier.try_wait.parity.acquire.cta.shared::cta.b64 p, [%1], %2;\n\t"
                 "selp.b32 %0, 1, 0, p;\n\t}"
                 : "=r"(done) : "r"(m), "r"(parity) : "memory");
    if (!done) {
        asm volatile("{\n\t.reg .pred P1;\n\t"
                     "W_%=:\n\t"
                     "mbarrier.try_wait.parity.acquire.cta.shared::cta.b64 P1, [%0], %1, 0x989680;\n\t"
                     "@P1 bra.uni D_%=;\n\t"
                     "bra.uni W_%=;\n\t"
                     "D_%=:\n\t}" :: "r"(m), "r"(parity) : "memory");
    }
}
__device__ __forceinline__ void ldmx4(uint32_t* r, uint32_t addr) {
    asm volatile("ldmatrix.sync.aligned.m8n8.x4.shared.b16 {%0,%1,%2,%3}, [%4];"
                 : "=r"(r[0]), "=r"(r[1]), "=r"(r[2]), "=r"(r[3]) : "r"(addr));
}
__device__ __forceinline__ void mma_f16(float& d0, float& d1, float& d2, float& d3,
                                        uint32_t a0, uint32_t a1, uint32_t a2, uint32_t a3,
                                        uint32_t b0, uint32_t b1) {
    asm volatile("mma.sync.aligned.m16n8k16.row.col.f32.f16.f16.f32 "
                 "{%0,%1,%2,%3}, {%4,%5,%6,%7}, {%8,%9}, {%0,%1,%2,%3};"
                 : "+f"(d0), "+f"(d1), "+f"(d2), "+f"(d3)
                 : "r"(a0), "r"(a1), "r"(a2), "r"(a3), "r"(b0), "r"(b1));
}

__global__ __launch_bounds__(NTHREADS, 1)
void conv25d_mma_kernel(const float* __restrict__ inp, const float* __restrict__ dep,
                        const float* __restrict__ bias, const void* __restrict__ fptr,
                        float* __restrict__ out) {
    extern __shared__ char smem[];
    const uint32_t sb = smem_u32(smem);
    const int tid  = threadIdx.x;
    const int wid  = tid >> 5;
    const int lane = tid & 31;
    const int mw   = wid & 7;      // 4 x-quarters x 2 row-slots
    const int nw   = wid >> 3;     // N warp: o [nw*32, nw*32+32)
    const int rs   = mw >> 2;      // row-slot within a pass (0/1)
    const int y0   = blockIdx.x * 4;
    const int b    = blockIdx.y;

    float*     s_d    = (float*)(smem + OFF_D);
    float*     s_lo   = (float*)(smem + OFF_LO);
    float*     s_hi   = (float*)(smem + OFF_HI);
    float*     s_bias = (float*)(smem + OFF_BIAS);
    uint32_t*  s_in   = (uint32_t*)(smem + OFF_IN);
    const uint32_t mb_full  = sb + OFF_FULL;
    const uint32_t mb_empty = sb + OFF_EMPTY;
    const uint32_t wsm      = sb + OFF_W;

    if (tid == 0) {
        for (int s = 0; s < 2; s++) {
            mbar_init(mb_full + 8 * s, 1);
            mbar_init(mb_empty + 8 * s, 16);   // one arrive per warp
        }
    }
    __syncthreads();
    if (tid == 0) {
        asm volatile("fence.proxy.async.shared::cta;" ::: "memory");
        for (int q = 0; q < 2; q++) {
            mbar_expect_tx(mb_full + 8 * q, GROUP_BYTES);
            bulk_cp(wsm + q * GROUP_BYTES, g_wf + q * 6144, GROUP_BYTES, mb_full + 8 * q);
        }
    }

    // scalar f (int or float bits)
    unsigned fu = *reinterpret_cast<const unsigned*>(fptr);
    float fval = (fu > 0u && fu < (1u << 24)) ? (float)fu : __uint_as_float(fu);

    // depth rows y0-1..y0+4 (padded), bin bounds for 4 rows, bias
    const float* db = dep + (long)b * HH * WW;
    for (int i = tid; i < 6 * XPAD; i += NTHREADS) {
        int xx = i % XPAD, r = i / XPAD;
        int gx = xx - 1, gy = y0 + r - 1;
        float v = 0.f;
        if ((unsigned)gx < (unsigned)WW && (unsigned)gy < (unsigned)HH) v = db[gy * WW + gx];
        s_d[i] = v;
    }
    {
        int x = tid & 127, yy = y0 + (tid >> 7);   // tid covers 4 rows x 128
        float d0 = db[yy * WW + x];
        float s0 = __fdiv_rn(d0, fval);
        float hv = __fmul_rn(s0, 0.5f);
#pragma unroll
        for (int h = 0; h < 3; h++) {
            float z0 = __fadd_rn(d0, __fmul_rn((float)(h - 1), s0));
            s_lo[h * 512 + tid] = __fsub_rn(z0, hv);
            s_hi[h * 512 + tid] = __fadd_rn(z0, hv);
        }
    }
    if (tid < 64) s_bias[tid] = bias[tid];

    // stage input rows y0-1..y0+4 as half2, layout [r][x][c2]
    const float* inb = inp + ((long)b * CIN) * HH * WW;
    for (int i = tid; i < 6 * 32 * XPAD; i += NTHREADS) {
        int xx = i % XPAD;
        int c2 = (i / XPAD) % 32;
        int r  = i / (XPAD * 32);
        int gx = xx - 1, gy = y0 + r - 1;
        uint32_t u = 0u;
        if ((unsigned)gx < (unsigned)WW && (unsigned)gy < (unsigned)HH) {
            float f0 = inb[((2 * c2) * HH + gy) * WW + gx];
            float f1 = inb[((2 * c2 + 1) * HH + gy) * WW + gx];
            __half2 p = __floats2half2_rn(f0, f1);
            u = *reinterpret_cast<uint32_t*>(&p);
        }
        s_in[(r * XPAD + xx) * XPC2 + c2] = u;
    }
    __syncthreads();

    // lane address components
    const int t4     = lane >> 3;
    const int x_lane = (mw & 3) * 32 + (t4 & 1) * 8 + (lane & 7);  // ldmatrix x
    const int c2off  = (t4 >> 1) * 4;
    const int x4     = (mw & 3) * 32 + (lane >> 2);                // mask-owner x

#pragma unroll 1
    for (int pass = 0; pass < 2; pass++) {
        const int row4 = 2 * pass + rs;

        float d[2][4][4];
#pragma unroll
        for (int mt = 0; mt < 2; mt++)
#pragma unroll
            for (int nt = 0; nt < 4; nt++)
#pragma unroll
                for (int r = 0; r < 4; r++) d[mt][nt][r] = 0.f;

#pragma unroll 1
        for (int tap = 0; tap < 9; tap++) {
            const int ky = tap / 3, kx = tap % 3;
            const int q  = pass * 9 + tap;
            const int s  = q & 1;

            // one wait per tap (group of 3 h-tiles)
            mbar_wait(mb_full + 8 * s, (q >> 1) & 1);
            const uint2* bt0 = (const uint2*)(smem + OFF_W + s * GROUP_BYTES) +
                               (nw * 4) * 32 + lane;

            // hoist this tap's A fragments: 8 ldmatrix.x4
            uint32_t A[4][2][4];
            const uint32_t abase = sb + OFF_IN +
                4u * (uint32_t)(((row4 + ky) * XPAD + x_lane + kx) * XPC2 + c2off);
#pragma unroll
            for (int kc = 0; kc < 4; kc++)
#pragma unroll
                for (int mt = 0; mt < 2; mt++)
                    ldmx4(A[kc][mt], abase + 4u * (uint32_t)(mt * 16 * XPC2 + kc * 8));

            // masks for this tap
            uint32_t msk[3][4];
#pragma unroll
            for (int i = 0; i < 4; i++) {
                float dw = s_d[(row4 + ky) * XPAD + x4 + i * 8 + kx];
                int pg = row4 * 128 + x4 + i * 8;
#pragma unroll
                for (int h = 0; h < 3; h++) {
                    float lo = s_lo[h * 512 + pg];
                    float hi = s_hi[h * 512 + pg];
                    msk[h][i] = (dw >= lo && dw < hi) ? 0xFFFFFFFFu : 0u;
                }
            }

            // software-pipelined B + MMA over 12 (h,kc) steps
            uint2 bf_cur[4], bf_next[4];
#pragma unroll
            for (int nt = 0; nt < 4; nt++) bf_next[nt] = bt0[nt * 32];

#pragma unroll
            for (int step = 0; step < 12; step++) {
                const int h  = step >> 2;
                const int kc = step & 3;
#pragma unroll
                for (int nt = 0; nt < 4; nt++) bf_cur[nt] = bf_next[nt];
                if (step < 11) {
                    const int h2  = (step + 1) >> 2;
                    const int kc2 = (step + 1) & 3;
                    const uint2* bp = bt0 + h2 * (TILE_BYTES / 8) + (kc2 * 8) * 32;
#pragma unroll
                    for (int nt = 0; nt < 4; nt++) bf_next[nt] = bp[nt * 32];
                }
#pragma unroll
                for (int mt = 0; mt < 2; mt++) {
                    uint32_t a0 = A[kc][mt][0] & msk[h][2 * mt];
                    uint32_t a1 = A[kc][mt][1] & msk[h][2 * mt + 1];
                    uint32_t a2 = A[kc][mt][2] & msk[h][2 * mt];
                    uint32_t a3 = A[kc][mt][3] & msk[h][2 * mt + 1];
#pragma unroll
                    for (int nt = 0; nt < 4; nt++)
                        mma_f16(d[mt][nt][0], d[mt][nt][1], d[mt][nt][2], d[mt][nt][3],
                                a0, a1, a2, a3, bf_cur[nt].x, bf_cur[nt].y);
                }
            }

            // release this group (one arrive per warp)
            if (lane == 0) mbar_arrive(mb_empty + 8 * s);
            // producer: refill this slot with group q+2
            if (tid == 0) {
                int qn = q + 2;
                if (qn < NQ) {
                    mbar_wait(mb_empty + 8 * s, (q >> 1) & 1);
                    mbar_expect_tx(mb_full + 8 * s, GROUP_BYTES);
                    bulk_cp(wsm + s * GROUP_BYTES, g_wf + (qn % 9) * 6144, GROUP_BYTES,
                            mb_full + 8 * s);
                }
            }
        }

        // epilogue for this pass: bias + store. out[b][o][y0+row4][px]
        float* ob = out + ((long)b * COUT * HH + (y0 + row4)) * WW;
#pragma unroll
        for (int mt = 0; mt < 2; mt++) {
            int pxr = (mw & 3) * 32 + mt * 16 + (lane >> 2);
#pragma unroll
            for (int nt = 0; nt < 4; nt++) {
                int o = nw * 32 + nt * 8 + 2 * (lane & 3);
                float b0 = s_bias[o], b1 = s_bias[o + 1];
                float* p0 = ob + (long)o * HH * WW + pxr;
                float* p1 = p0 + HH * WW;
                p0[0] = d[mt][nt][0] + b0;
                p1[0] = d[mt][nt][1] + b1;
                p0[8] = d[mt][nt][2] + b0;
                p1[8] = d[mt][nt][3] + b1;
            }
        }
    }
}

extern "C" void kernel_launch(void* const* d_in, const int* in_sizes, int n_in,
                              void* d_out, int out_size) {
    const float* inputs = (const float*)d_in[0];
    const float* depth  = (const float*)d_in[1];
    const float* weight = (const float*)d_in[2];
    const float* bias   = (const float*)d_in[3];
    const void*  f      = d_in[4];
    float* out = (float*)d_out;

    prep_w_kernel<<<(27 * 2048 + 255) / 256, 256>>>(weight);

    cudaFuncSetAttribute(conv25d_mma_kernel, cudaFuncAttributeMaxDynamicSharedMemorySize,
                         SMEM_TOTAL);
    dim3 grid(HH / 4, BB);
    conv25d_mma_kernel<<<grid, NTHREADS, SMEM_TOTAL>>>(inputs, depth, bias, f, out);
}

// round 13
// speedup vs baseline: 1.2527x; 1.0419x over previous
#include <cuda_runtime.h>
#include <cuda_fp16.h>
#include <cstdint>

#define CIN 64
#define COUT 64
#define HH 128
#define WW 128
#define BB 4
#define NTHREADS 512
#define XPAD 136            // x extent incl. halo/pad
#define XPC2 36             // words per x in s_in (32 c2 + 4 pad) -> ldmatrix conflict-free
#define TILE_BYTES 8192
#define GROUP_BYTES 24576   // 3 h-tiles, one mbarrier
#define NQ 18               // 2 passes x 9 tap-groups

// ---- smem byte offsets ----
#define OFF_FULL  0         // 2 x 8B
#define OFF_EMPTY 16        // 2 x 8B
#define OFF_D     64        // 6 x 136 floats = 3264
#define OFF_LO    3328      // 3 x 512 floats = 6144
#define OFF_HI    9472      // 3 x 512 floats = 6144
#define OFF_BIAS  15616     // 64 floats
#define OFF_IN    15872     // 6 rows x 136 x x 36 words = 117504 B  [r][x][c2]
#define OFF_W     133376    // 2 groups x 24576 B = 49152
#define SMEM_TOTAL 182528

// Fragment-ordered f16 weights: [tile=tap*3+h][kc4][nt8][lane32][j2] (u32 = half2)
__device__ uint32_t g_wf[27 * 2048];

__global__ void prep_w_kernel(const float* __restrict__ w) {
    int idx = blockIdx.x * blockDim.x + threadIdx.x;
    if (idx >= 27 * 2048) return;
    int j    = idx & 1;
    int lane = (idx >> 1) & 31;
    int nt   = (idx >> 6) & 7;
    int kc   = (idx >> 9) & 3;
    int tile = idx >> 11;
    int h = tile % 3, tap = tile / 3;
    int k0 = kc * 16 + (lane & 3) * 2 + j * 8;
    int o  = nt * 8 + (lane >> 2);
    // source layout: [h][o][c][ky][kx]
    float v0 = w[(((h * COUT + o) * CIN + k0) * 9) + tap];
    float v1 = w[(((h * COUT + o) * CIN + k0 + 1) * 9) + tap];
    __half2 p = __floats2half2_rn(v0, v1);
    g_wf[idx] = *reinterpret_cast<uint32_t*>(&p);
}

// ---- PTX helpers ----
__device__ __forceinline__ uint32_t smem_u32(const void* p) {
    uint32_t a;
    asm("{ .reg .u64 t; cvta.to.shared.u64 t, %1; cvt.u32.u64 %0, t; }" : "=r"(a) : "l"(p));
    return a;
}
__device__ __forceinline__ void mbar_init(uint32_t m, uint32_t cnt) {
    asm volatile("mbarrier.init.shared.b64 [%0], %1;" :: "r"(m), "r"(cnt) : "memory");
}
__device__ __forceinline__ void mbar_arrive(uint32_t m) {
    asm volatile("mbarrier.arrive.shared.b64 _, [%0];" :: "r"(m) : "memory");
}
__device__ __forceinline__ void mbar_expect_tx(uint32_t m, uint32_t bytes) {
    asm volatile("mbarrier.arrive.expect_tx.shared.b64 _, [%0], %1;" :: "r"(m), "r"(bytes) : "memory");
}
__device__ __forceinline__ void bulk_cp(uint32_t dst, const void* src, uint32_t bytes, uint32_t m) {
    asm volatile("cp.async.bulk.shared::cta.global.mbarrier::complete_tx::bytes [%0], [%1], %2, [%3];"
                 :: "r"(dst), "l"(src), "r"(bytes), "r"(m) : "memory");
}
__device__ __forceinline__ void mbar_wait(uint32_t m, uint32_t parity) {
    uint32_t done;
    asm volatile("{\n\t.reg .pred p;\n\t"
                 "mbarrier.try_wait.parity.acquire.cta.shared::cta.b64 p, [%1], %2;\n\t"
                 "selp.b32 %0, 1, 0, p;\n\t}"
                 : "=r"(done) : "r"(m), "r"(parity) : "memory");
    if (!done) {
        asm volatile("{\n\t.reg .pred P1;\n\t"
                     "W_%=:\n\t"
                     "mbarrier.try_wait.parity.acquire.cta.shared::cta.b64 P1, [%0], %1, 0x989680;\n\t"
                     "@P1 bra.uni D_%=;\n\t"
                     "bra.uni W_%=;\n\t"
                     "D_%=:\n\t}" :: "r"(m), "r"(parity) : "memory");
    }
}
__device__ __forceinline__ void ldmx4(uint32_t* r, uint32_t addr) {
    asm volatile("ldmatrix.sync.aligned.m8n8.x4.shared.b16 {%0,%1,%2,%3}, [%4];"
                 : "=r"(r[0]), "=r"(r[1]), "=r"(r[2]), "=r"(r[3]) : "r"(addr));
}
// NOTE: non-volatile — registers-only op, data deps enforce correctness,
// lets the compiler interleave MMAs with B-loads and across steps/taps.
__device__ __forceinline__ void mma_f16(float& d0, float& d1, float& d2, float& d3,
                                        uint32_t a0, uint32_t a1, uint32_t a2, uint32_t a3,
                                        uint32_t b0, uint32_t b1) {
    asm("mma.sync.aligned.m16n8k16.row.col.f32.f16.f16.f32 "
        "{%0,%1,%2,%3}, {%4,%5,%6,%7}, {%8,%9}, {%0,%1,%2,%3};"
        : "+f"(d0), "+f"(d1), "+f"(d2), "+f"(d3)
        : "r"(a0), "r"(a1), "r"(a2), "r"(a3), "r"(b0), "r"(b1));
}

__global__ __launch_bounds__(NTHREADS, 1)
void conv25d_mma_kernel(const float* __restrict__ inp, const float* __restrict__ dep,
                        const float* __restrict__ bias, const void* __restrict__ fptr,
                        float* __restrict__ out) {
    extern __shared__ char smem[];
    const uint32_t sb = smem_u32(smem);
    const int tid  = threadIdx.x;
    const int wid  = tid >> 5;
    const int lane = tid & 31;
    const int mw   = wid & 7;      // 4 x-quarters x 2 row-slots
    const int nw   = wid >> 3;     // N warp: o [nw*32, nw*32+32)
    const int rs   = mw >> 2;      // row-slot within a pass (0/1)
    const int y0   = blockIdx.x * 4;
    const int b    = blockIdx.y;

    float*     s_d    = (float*)(smem + OFF_D);
    float*     s_lo   = (float*)(smem + OFF_LO);
    float*     s_hi   = (float*)(smem + OFF_HI);
    float*     s_bias = (float*)(smem + OFF_BIAS);
    uint32_t*  s_in   = (uint32_t*)(smem + OFF_IN);
    const uint32_t mb_full  = sb + OFF_FULL;
    const uint32_t mb_empty = sb + OFF_EMPTY;
    const uint32_t wsm      = sb + OFF_W;

    if (tid == 0) {
        for (int s = 0; s < 2; s++) {
            mbar_init(mb_full + 8 * s, 1);
            mbar_init(mb_empty + 8 * s, 16);   // one arrive per warp
        }
    }
    __syncthreads();
    if (tid == 0) {
        asm volatile("fence.proxy.async.shared::cta;" ::: "memory");
        for (int q = 0; q < 2; q++) {
            mbar_expect_tx(mb_full + 8 * q, GROUP_BYTES);
            bulk_cp(wsm + q * GROUP_BYTES, g_wf + q * 6144, GROUP_BYTES, mb_full + 8 * q);
        }
    }

    // scalar f (int or float bits)
    unsigned fu = *reinterpret_cast<const unsigned*>(fptr);
    float fval = (fu > 0u && fu < (1u << 24)) ? (float)fu : __uint_as_float(fu);

    // depth rows y0-1..y0+4 (padded), bin bounds for 4 rows, bias
    const float* db = dep + (long)b * HH * WW;
    for (int i = tid; i < 6 * XPAD; i += NTHREADS) {
        int xx = i % XPAD, r = i / XPAD;
        int gx = xx - 1, gy = y0 + r - 1;
        float v = 0.f;
        if ((unsigned)gx < (unsigned)WW && (unsigned)gy < (unsigned)HH) v = db[gy * WW + gx];
        s_d[i] = v;
    }
    {
        int x = tid & 127, yy = y0 + (tid >> 7);   // tid covers 4 rows x 128
        float d0 = db[yy * WW + x];
        float s0 = __fdiv_rn(d0, fval);
        float hv = __fmul_rn(s0, 0.5f);
#pragma unroll
        for (int h = 0; h < 3; h++) {
            float z0 = __fadd_rn(d0, __fmul_rn((float)(h - 1), s0));
            s_lo[h * 512 + tid] = __fsub_rn(z0, hv);
            s_hi[h * 512 + tid] = __fadd_rn(z0, hv);
        }
    }
    if (tid < 64) s_bias[tid] = bias[tid];

    // stage input rows y0-1..y0+4 as half2, layout [r][x][c2]
    const float* inb = inp + ((long)b * CIN) * HH * WW;
    for (int i = tid; i < 6 * 32 * XPAD; i += NTHREADS) {
        int xx = i % XPAD;
        int c2 = (i / XPAD) % 32;
        int r  = i / (XPAD * 32);
        int gx = xx - 1, gy = y0 + r - 1;
        uint32_t u = 0u;
        if ((unsigned)gx < (unsigned)WW && (unsigned)gy < (unsigned)HH) {
            float f0 = inb[((2 * c2) * HH + gy) * WW + gx];
            float f1 = inb[((2 * c2 + 1) * HH + gy) * WW + gx];
            __half2 p = __floats2half2_rn(f0, f1);
            u = *reinterpret_cast<uint32_t*>(&p);
        }
        s_in[(r * XPAD + xx) * XPC2 + c2] = u;
    }
    __syncthreads();

    // lane address components
    const int t4     = lane >> 3;
    const int x_lane = (mw & 3) * 32 + (t4 & 1) * 8 + (lane & 7);  // ldmatrix x
    const int c2off  = (t4 >> 1) * 4;
    const int x4     = (mw & 3) * 32 + (lane >> 2);                // mask-owner x

#pragma unroll 1
    for (int pass = 0; pass < 2; pass++) {
        const int row4 = 2 * pass + rs;

        float d[2][4][4];
#pragma unroll
        for (int mt = 0; mt < 2; mt++)
#pragma unroll
            for (int nt = 0; nt < 4; nt++)
#pragma unroll
                for (int r = 0; r < 4; r++) d[mt][nt][r] = 0.f;

#pragma unroll 1
        for (int tap = 0; tap < 9; tap++) {
            const int ky = tap / 3, kx = tap % 3;
            const int q  = pass * 9 + tap;
            const int s  = q & 1;

            // masks for this tap (issued first: LDS latency overlaps ldmatrix below)
            uint32_t msk[3][4];
#pragma unroll
            for (int i = 0; i < 4; i++) {
                float dw = s_d[(row4 + ky) * XPAD + x4 + i * 8 + kx];
                int pg = row4 * 128 + x4 + i * 8;
#pragma unroll
                for (int h = 0; h < 3; h++) {
                    float lo = s_lo[h * 512 + pg];
                    float hi = s_hi[h * 512 + pg];
                    msk[h][i] = (dw >= lo && dw < hi) ? 0xFFFFFFFFu : 0u;
                }
            }

            // one wait per tap (group of 3 h-tiles)
            mbar_wait(mb_full + 8 * s, (q >> 1) & 1);
            const uint2* bt0 = (const uint2*)(smem + OFF_W + s * GROUP_BYTES) +
                               (nw * 4) * 32 + lane;

            // hoist this tap's A fragments: 8 ldmatrix.x4
            uint32_t A[4][2][4];
            const uint32_t abase = sb + OFF_IN +
                4u * (uint32_t)(((row4 + ky) * XPAD + x_lane + kx) * XPC2 + c2off);
#pragma unroll
            for (int kc = 0; kc < 4; kc++)
#pragma unroll
                for (int mt = 0; mt < 2; mt++)
                    ldmx4(A[kc][mt], abase + 4u * (uint32_t)(mt * 16 * XPC2 + kc * 8));

            // MOV-free ping-pong B pipeline over 12 (h,kc) steps
            uint2 bf[2][4];
#pragma unroll
            for (int nt = 0; nt < 4; nt++) bf[0][nt] = bt0[nt * 32];

#pragma unroll
            for (int step = 0; step < 12; step++) {
                const int h   = step >> 2;
                const int kc  = step & 3;
                const int cur = step & 1;
                if (step < 11) {
                    const int s2 = step + 1;
                    const uint2* bp = bt0 + (s2 >> 2) * (TILE_BYTES / 8) + ((s2 & 3) * 8) * 32;
#pragma unroll
                    for (int nt = 0; nt < 4; nt++) bf[cur ^ 1][nt] = bp[nt * 32];
                }
#pragma unroll
                for (int mt = 0; mt < 2; mt++) {
                    uint32_t a0 = A[kc][mt][0] & msk[h][2 * mt];
                    uint32_t a1 = A[kc][mt][1] & msk[h][2 * mt + 1];
                    uint32_t a2 = A[kc][mt][2] & msk[h][2 * mt];
                    uint32_t a3 = A[kc][mt][3] & msk[h][2 * mt + 1];
#pragma unroll
                    for (int nt = 0; nt < 4; nt++)
                        mma_f16(d[mt][nt][0], d[mt][nt][1], d[mt][nt][2], d[mt][nt][3],
                                a0, a1, a2, a3, bf[cur][nt].x, bf[cur][nt].y);
                }
            }

            // release this group (one arrive per warp)
            if (lane == 0) mbar_arrive(mb_empty + 8 * s);
            // producer: refill this slot with group q+2
            if (tid == 0) {
                int qn = q + 2;
                if (qn < NQ) {
                    mbar_wait(mb_empty + 8 * s, (q >> 1) & 1);
                    mbar_expect_tx(mb_full + 8 * s, GROUP_BYTES);
                    bulk_cp(wsm + s * GROUP_BYTES, g_wf + (qn % 9) * 6144, GROUP_BYTES,
                            mb_full + 8 * s);
                }
            }
        }

        // epilogue for this pass: bias + store. out[b][o][y0+row4][px]
        float* ob = out + ((long)b * COUT * HH + (y0 + row4)) * WW;
#pragma unroll
        for (int mt = 0; mt < 2; mt++) {
            int pxr = (mw & 3) * 32 + mt * 16 + (lane >> 2);
#pragma unroll
            for (int nt = 0; nt < 4; nt++) {
                int o = nw * 32 + nt * 8 + 2 * (lane & 3);
                float b0 = s_bias[o], b1 = s_bias[o + 1];
                float* p0 = ob + (long)o * HH * WW + pxr;
                float* p1 = p0 + HH * WW;
                p0[0] = d[mt][nt][0] + b0;
                p1[0] = d[mt][nt][1] + b1;
                p0[8] = d[mt][nt][2] + b0;
                p1[8] = d[mt][nt][3] + b1;
            }
        }
    }
}

extern "C" void kernel_launch(void* const* d_in, const int* in_sizes, int n_in,
                              void* d_out, int out_size) {
    const float* inputs = (const float*)d_in[0];
    const float* depth  = (const float*)d_in[1];
    const float* weight = (const float*)d_in[2];
    const float* bias   = (const float*)d_in[3];
    const void*  f      = d_in[4];
    float* out = (float*)d_out;

    prep_w_kernel<<<(27 * 2048 + 255) / 256, 256>>>(weight);

    cudaFuncSetAttribute(conv25d_mma_kernel, cudaFuncAttributeMaxDynamicSharedMemorySize,
                         SMEM_TOTAL);
    dim3 grid(HH / 4, BB);
    conv25d_mma_kernel<<<grid, NTHREADS, SMEM_TOTAL>>>(inputs, depth, bias, f, out);
}